// round 1
// baseline (speedup 1.0000x reference)
#include <cuda_runtime.h>
#include <cstdint>

typedef unsigned long long ull;

#define H     51
#define G4    (4*H)       // 204 real gates
#define GP    256         // padded gate count
#define GROW  260         // g row stride (floats) -> conflict-free gate reads
#define K1    52          // padded K for layer1 (51 -> 52)
#define K2    104         // padded K for layer2 (102 -> 104)
#define HROW  212         // hdup row stride (floats): 2*104=208 -> 212
#define BB    8           // batch per block
#define TSEQ  512
#define FUT   64
#define TTOT  (TSEQ + FUT)
#define NT    128         // threads per block

// ---- smem layout (float offsets) ----
#define OFF_W1T  0
#define SZ_W1T   (K1*GP)                  // 13312
#define OFF_W2T  (OFF_W1T + SZ_W1T)
#define SZ_W2T   (K2*GP)                  // 26624
#define OFF_WX   (OFF_W2T + SZ_W2T)       // 39936
#define OFF_B1   (OFF_WX + GP)
#define OFF_B2   (OFF_B1 + GP)
#define OFF_WL   (OFF_B2 + GP)
#define OFF_IN   (OFF_WL + 64)
#define SZ_IN    (BB*TSEQ)                // 4096
#define OFF_HD   (OFF_IN + SZ_IN)
#define SZ_HD    (BB*HROW)                // 1696
#define OFF_G    (OFF_HD + SZ_HD)
#define SZ_G     (BB*GROW)                // 2080
#define OFF_OUT  (OFF_G + SZ_G)
#define OFF_BL   (OFF_OUT + 8)
#define SMEM_FLOATS (OFF_BL + 4)
#define SMEM_BYTES  (SMEM_FLOATS * 4)

__device__ __forceinline__ ull ffma2(ull a, ull b, ull c) {
    ull d;
    asm("fma.rn.f32x2 %0, %1, %2, %3;" : "=l"(d) : "l"(a), "l"(b), "l"(c));
    return d;
}

__device__ __forceinline__ ull dup2(float v) {
    ull r;
    unsigned u = __float_as_uint(v);
    asm("mov.b64 %0, {%1, %2};" : "=l"(r) : "r"(u), "r"(u));
    return r;
}

__device__ __forceinline__ float fsig(float x) {
    float e = __expf(-x);
    return __fdividef(1.0f, 1.0f + e);
}

__device__ __forceinline__ float ftanh_acc(float x) {
    float a = fabsf(x);
    float e = __expf(-2.0f * a);           // <= 1, no overflow
    float r = __fdividef(1.0f - e, 1.0f + e);
    return copysignf(r, x);
}

// out[j] += sum_k WT[k][j] * h[k], over padded K=2*KP, for 4 batch elems,
// 4 consecutive j's per lane (2 f32x2 accumulators per batch elem).
// hd points at this warp's batch-group base in the duplicated-h buffer.
template<int KP>
__device__ __forceinline__ void matvec(const float* __restrict__ WT,
                                       const float* __restrict__ hd,
                                       ull acc0[4], ull acc1[4], int j0)
{
    #pragma unroll 4
    for (int kp = 0; kp < KP; ++kp) {
        ulonglong2 w0 = *reinterpret_cast<const ulonglong2*>(WT + (2*kp  )*GP + j0);
        ulonglong2 w1 = *reinterpret_cast<const ulonglong2*>(WT + (2*kp+1)*GP + j0);
        #pragma unroll
        for (int b = 0; b < 4; ++b) {
            // hv = (h[2kp],h[2kp], h[2kp+1],h[2kp+1]) — pre-duplicated pairs
            ulonglong2 hv = *reinterpret_cast<const ulonglong2*>(hd + b*HROW + 4*kp);
            acc0[b] = ffma2(w0.x, hv.x, acc0[b]);
            acc1[b] = ffma2(w0.y, hv.x, acc1[b]);
            acc0[b] = ffma2(w1.x, hv.y, acc0[b]);
            acc1[b] = ffma2(w1.y, hv.y, acc1[b]);
        }
    }
}

// gate nonlinearity phase: 408 (b,h) tasks over 128 threads; c state in regs.
__device__ __forceinline__ void gates(const float* __restrict__ g,
                                      float* __restrict__ hd,
                                      float creg[4], int hoff, int tid)
{
    #pragma unroll
    for (int i = 0; i < 4; ++i) {
        int tt = tid + i*NT;
        if (tt < BB*H) {
            int b = tt & 7, h = tt >> 3;
            const float* gr = g + b*GROW;
            float gi = gr[h];
            float gf = gr[H + h];
            float gg = gr[2*H + h];
            float go = gr[3*H + h];
            float c = fsig(gf)*creg[i] + fsig(gi)*ftanh_acc(gg);
            float hn = fsig(go)*ftanh_acc(c);
            creg[i] = c;
            *reinterpret_cast<float2*>(hd + b*HROW + 2*(hoff + h)) = make_float2(hn, hn);
        }
    }
}

__global__ void __launch_bounds__(NT, 1)
lstm_seq_kernel(const float* __restrict__ input,
                const float* __restrict__ Wih1, const float* __restrict__ Whh1,
                const float* __restrict__ bih1, const float* __restrict__ bhh1,
                const float* __restrict__ Wih2, const float* __restrict__ Whh2,
                const float* __restrict__ bih2, const float* __restrict__ bhh2,
                const float* __restrict__ Wl,   const float* __restrict__ bl,
                float* __restrict__ out)
{
    extern __shared__ __align__(16) float sm[];
    const int tid = threadIdx.x;
    const int b0  = blockIdx.x * BB;

    // ---------- one-time prep: stage transposed/padded weights & inputs ----------
    for (int idx = tid; idx < SZ_W1T; idx += NT) {
        int k = idx >> 8, j = idx & 255;
        sm[OFF_W1T + idx] = (j < G4 && k < H) ? Whh1[j*H + k] : 0.0f;
    }
    for (int idx = tid; idx < SZ_W2T; idx += NT) {
        int k = idx >> 8, j = idx & 255;
        float v = 0.0f;
        if (j < G4) {
            if (k < H)        v = Wih2[j*H + k];
            else if (k < 2*H) v = Whh2[j*H + (k - H)];
        }
        sm[OFF_W2T + idx] = v;
    }
    for (int j = tid; j < GP; j += NT) {
        bool r = (j < G4);
        sm[OFF_WX + j] = r ? Wih1[j] : 0.0f;
        sm[OFF_B1 + j] = r ? (bih1[j] + bhh1[j]) : 0.0f;
        sm[OFF_B2 + j] = r ? (bih2[j] + bhh2[j]) : 0.0f;
    }
    if (tid < 64) sm[OFF_WL + tid] = (tid < H) ? Wl[tid] : 0.0f;
    for (int idx = tid; idx < SZ_IN; idx += NT)
        sm[OFF_IN + idx] = input[b0*TSEQ + idx];     // 8 contiguous rows
    for (int idx = tid; idx < SZ_HD; idx += NT) sm[OFF_HD + idx] = 0.0f;
    for (int idx = tid; idx < SZ_G;  idx += NT) sm[OFF_G  + idx] = 0.0f;
    if (tid < 8)   sm[OFF_OUT + tid] = 0.0f;
    if (tid == 0)  sm[OFF_BL] = bl[0];
    __syncthreads();

    float c1r[4] = {0.f, 0.f, 0.f, 0.f};
    float c2r[4] = {0.f, 0.f, 0.f, 0.f};

    const int wid  = tid >> 5, lane = tid & 31;
    const int bq   = (wid & 1) * 4;                 // batch group base (0 or 4)
    const int j0   = (wid >> 1) * 128 + lane * 4;   // j slice base
    const float* W1T = sm + OFF_W1T;
    const float* W2T = sm + OFF_W2T;
    float* hd = sm + OFF_HD;
    float* g  = sm + OFF_G;
    const float* hdw = hd + bq*HROW;

    for (int t = 0; t < TTOT; ++t) {
        // ---- matvec layer 1: g = x*wx + b1 + Whh1 @ h1 ----
        {
            ulonglong2 bv  = *reinterpret_cast<const ulonglong2*>(sm + OFF_B1 + j0);
            ulonglong2 wxv = *reinterpret_cast<const ulonglong2*>(sm + OFF_WX + j0);
            ull acc0[4], acc1[4];
            #pragma unroll
            for (int b = 0; b < 4; ++b) {
                float x = (t < TSEQ) ? sm[OFF_IN + (bq + b)*TSEQ + t]
                                     : sm[OFF_OUT + bq + b];
                ull xx = dup2(x);
                acc0[b] = ffma2(wxv.x, xx, bv.x);
                acc1[b] = ffma2(wxv.y, xx, bv.y);
            }
            matvec<K1/2>(W1T, hdw, acc0, acc1, j0);
            #pragma unroll
            for (int b = 0; b < 4; ++b)
                *reinterpret_cast<ulonglong2*>(g + (bq + b)*GROW + j0) =
                    make_ulonglong2(acc0[b], acc1[b]);
        }
        __syncthreads();

        gates(g, hd, c1r, 0, tid);      // writes h1 (dup) into hdup[0..2H)
        __syncthreads();

        // ---- matvec layer 2: g = b2 + [Wih2|Whh2] @ [h1;h2] ----
        {
            ulonglong2 bv = *reinterpret_cast<const ulonglong2*>(sm + OFF_B2 + j0);
            ull acc0[4], acc1[4];
            #pragma unroll
            for (int b = 0; b < 4; ++b) { acc0[b] = bv.x; acc1[b] = bv.y; }
            matvec<K2/2>(W2T, hdw, acc0, acc1, j0);
            #pragma unroll
            for (int b = 0; b < 4; ++b)
                *reinterpret_cast<ulonglong2*>(g + (bq + b)*GROW + j0) =
                    make_ulonglong2(acc0[b], acc1[b]);
        }
        __syncthreads();

        gates(g, hd, c2r, H, tid);      // writes h2 (dup) into hdup[2H..4H)
        __syncthreads();

        // ---- output: out = h2 . Wl + bl ----
        {
            #pragma unroll
            for (int r = 0; r < 2; ++r) {
                int b = wid + r*4;
                float p = hd[b*HROW + 2*H + 2*lane] * sm[OFF_WL + lane];
                if (lane + 32 < H)
                    p += hd[b*HROW + 2*H + 2*(lane + 32)] * sm[OFF_WL + lane + 32];
                #pragma unroll
                for (int o = 16; o > 0; o >>= 1)
                    p += __shfl_xor_sync(0xffffffffu, p, o);
                if (lane == 0) {
                    float ov = p + sm[OFF_BL];
                    out[(b0 + b)*TTOT + t] = ov;
                    sm[OFF_OUT + b] = ov;   // feeds future-phase x
                }
            }
        }
        __syncthreads();
    }
}

extern "C" void kernel_launch(void* const* d_in, const int* in_sizes, int n_in,
                              void* d_out, int out_size)
{
    (void)n_in; (void)out_size;
    cudaFuncSetAttribute(lstm_seq_kernel,
                         cudaFuncAttributeMaxDynamicSharedMemorySize, SMEM_BYTES);
    int nblocks = in_sizes[0] / (TSEQ * BB);   // B / 8 = 128
    lstm_seq_kernel<<<nblocks, NT, SMEM_BYTES>>>(
        (const float*)d_in[0],  (const float*)d_in[1], (const float*)d_in[2],
        (const float*)d_in[3],  (const float*)d_in[4], (const float*)d_in[5],
        (const float*)d_in[6],  (const float*)d_in[7], (const float*)d_in[8],
        (const float*)d_in[9],  (const float*)d_in[10],
        (float*)d_out);
}

// round 2
// speedup vs baseline: 1.0008x; 1.0008x over previous
#include <cuda_runtime.h>
#include <cstdint>

typedef unsigned long long ull;

#define H     51
#define G4    (4*H)       // 204 real gates
#define GP    256         // padded gate count
#define GROW  260         // g row stride (floats)
#define HROW  212         // hdup row stride (floats): 2*104=208 -> 212
#define BB    8           // batch per block
#define TSEQ  512
#define FUT   64
#define TTOT  (TSEQ + FUT)
#define NT    256         // threads per block (8 warps)

// ---- smem layout (float offsets) ----
#define OFF_W1T  0
#define SZ_W1T   (52*GP)                  // 13312
#define OFF_W2T  (OFF_W1T + SZ_W1T)
#define SZ_W2T   (104*GP)                 // 26624
#define OFF_WX   (OFF_W2T + SZ_W2T)
#define OFF_B1   (OFF_WX + GP)
#define OFF_B2   (OFF_B1 + GP)
#define OFF_WL   (OFF_B2 + GP)
#define OFF_IN   (OFF_WL + 64)
#define SZ_IN    (BB*TSEQ)                // 4096
#define OFF_HD   (OFF_IN + SZ_IN)
#define SZ_HD    (BB*HROW)                // 1696
#define OFF_GA   (OFF_HD + SZ_HD)
#define SZ_G     (BB*GROW)                // 2080
#define OFF_GB   (OFF_GA + SZ_G)
#define OFF_OUT  (OFF_GB + SZ_G)
#define OFF_BL   (OFF_OUT + 8)
#define SMEM_FLOATS (OFF_BL + 4)
#define SMEM_BYTES  (SMEM_FLOATS * 4)

__device__ __forceinline__ ull ffma2(ull a, ull b, ull c) {
    ull d;
    asm("fma.rn.f32x2 %0, %1, %2, %3;" : "=l"(d) : "l"(a), "l"(b), "l"(c));
    return d;
}

__device__ __forceinline__ ull dup2(float v) {
    ull r;
    unsigned u = __float_as_uint(v);
    asm("mov.b64 %0, {%1, %2};" : "=l"(r) : "r"(u), "r"(u));
    return r;
}

__device__ __forceinline__ float fsig(float x) {
    float e = __expf(-x);
    return __fdividef(1.0f, 1.0f + e);
}

__device__ __forceinline__ float ftanh_acc(float x) {
    float a = fabsf(x);
    float e = __expf(-2.0f * a);           // <= 1, no overflow
    float r = __fdividef(1.0f - e, 1.0f + e);
    return copysignf(r, x);
}

// Partial matvec over NPAIR k-pairs: acc[b] += sum_k WT[k][j0..j0+1] * h[b][k]
// WT points at this warp's first k row; hd points at this warp's first h pair.
// Each weight LDS.64 feeds all 8 batch elements (read once per step chip-wide).
template<int NPAIR, int UNROLL>
__device__ __forceinline__ void matvec(const float* __restrict__ WT,
                                       const float* __restrict__ hd,
                                       ull acc[8], int j0)
{
    #pragma unroll UNROLL
    for (int kp = 0; kp < NPAIR; ++kp) {
        ull w0 = *reinterpret_cast<const ull*>(WT + (2*kp  )*GP + j0);
        ull w1 = *reinterpret_cast<const ull*>(WT + (2*kp+1)*GP + j0);
        #pragma unroll
        for (int b = 0; b < 8; ++b) {
            // (h[2kp],h[2kp], h[2kp+1],h[2kp+1]) — pre-duplicated pairs, broadcast
            ulonglong2 hv = *reinterpret_cast<const ulonglong2*>(hd + b*HROW + 4*kp);
            acc[b] = ffma2(w0, hv.x, acc[b]);
            acc[b] = ffma2(w1, hv.y, acc[b]);
        }
    }
}

// gate nonlinearity: 408 (b,h) tasks over 256 threads; sums the two K-half
// partial buffers (split-K reduction folded in); c state lives in registers.
__device__ __forceinline__ void gates(const float* __restrict__ gA,
                                      const float* __restrict__ gB,
                                      float* __restrict__ hd,
                                      float creg[2], int hoff, int tid)
{
    #pragma unroll
    for (int i = 0; i < 2; ++i) {
        int tt = tid + i*NT;
        if (tt < BB*H) {
            int b = tt & 7, h = tt >> 3;
            int base = b*GROW + h;
            float gi = gA[base      ] + gB[base      ];
            float gf = gA[base +   H] + gB[base +   H];
            float gg = gA[base + 2*H] + gB[base + 2*H];
            float go = gA[base + 3*H] + gB[base + 3*H];
            float c  = fsig(gf)*creg[i] + fsig(gi)*ftanh_acc(gg);
            float hn = fsig(go)*ftanh_acc(c);
            creg[i] = c;
            *reinterpret_cast<float2*>(hd + b*HROW + 2*(hoff + h)) = make_float2(hn, hn);
        }
    }
}

__global__ void __launch_bounds__(NT, 1)
lstm_seq_kernel(const float* __restrict__ input,
                const float* __restrict__ Wih1, const float* __restrict__ Whh1,
                const float* __restrict__ bih1, const float* __restrict__ bhh1,
                const float* __restrict__ Wih2, const float* __restrict__ Whh2,
                const float* __restrict__ bih2, const float* __restrict__ bhh2,
                const float* __restrict__ Wl,   const float* __restrict__ bl,
                float* __restrict__ out)
{
    extern __shared__ __align__(16) float sm[];
    const int tid = threadIdx.x;
    const int b0  = blockIdx.x * BB;

    // ---------- one-time prep: stage transposed/padded weights & inputs ----------
    for (int idx = tid; idx < SZ_W1T; idx += NT) {
        int k = idx >> 8, j = idx & 255;
        sm[OFF_W1T + idx] = (j < G4 && k < H) ? Whh1[j*H + k] : 0.0f;
    }
    for (int idx = tid; idx < SZ_W2T; idx += NT) {
        int k = idx >> 8, j = idx & 255;
        float v = 0.0f;
        if (j < G4) {
            if (k < H)        v = Wih2[j*H + k];
            else if (k < 2*H) v = Whh2[j*H + (k - H)];
        }
        sm[OFF_W2T + idx] = v;
    }
    for (int j = tid; j < GP; j += NT) {
        bool r = (j < G4);
        sm[OFF_WX + j] = r ? Wih1[j] : 0.0f;
        sm[OFF_B1 + j] = r ? (bih1[j] + bhh1[j]) : 0.0f;
        sm[OFF_B2 + j] = r ? (bih2[j] + bhh2[j]) : 0.0f;
    }
    if (tid < 64) sm[OFF_WL + tid] = (tid < H) ? Wl[tid] : 0.0f;
    for (int idx = tid; idx < SZ_IN; idx += NT)
        sm[OFF_IN + idx] = input[b0*TSEQ + idx];     // 8 contiguous rows
    for (int idx = tid; idx < SZ_HD; idx += NT) sm[OFF_HD + idx] = 0.0f;
    for (int idx = tid; idx < SZ_G;  idx += NT) { sm[OFF_GA + idx] = 0.0f; sm[OFF_GB + idx] = 0.0f; }
    if (tid < 8)   sm[OFF_OUT + tid] = 0.0f;
    if (tid == 0)  sm[OFF_BL] = bl[0];
    __syncthreads();

    float c1r[2] = {0.f, 0.f};
    float c2r[2] = {0.f, 0.f};

    const int wid  = tid >> 5, lane = tid & 31;
    const int js   = wid & 3;                // j-slice (4 x 64 gates)
    const int kh   = wid >> 2;               // K-half (split-K)
    const int j0   = js*64 + lane*2;         // 2 consecutive gates per lane
    float* gout = sm + (kh ? OFF_GB : OFF_GA);
    const float* W1T = sm + OFF_W1T + (kh*13)*2*GP;   // layer1: 13 k-pairs per half
    const float* W2T = sm + OFF_W2T + (kh*26)*2*GP;   // layer2: 26 k-pairs per half
    const float* hd1 = sm + OFF_HD + (kh*13)*4;
    const float* hd2 = sm + OFF_HD + (kh*26)*4;
    float* hd = sm + OFF_HD;

    for (int t = 0; t < TTOT; ++t) {
        // ---- matvec layer 1 (partial over this warp's K-half) ----
        {
            ull acc[8];
            if (kh == 0) {
                ull bv  = *reinterpret_cast<const ull*>(sm + OFF_B1 + j0);
                ull wxv = *reinterpret_cast<const ull*>(sm + OFF_WX + j0);
                #pragma unroll
                for (int b = 0; b < 8; ++b) {
                    float x = (t < TSEQ) ? sm[OFF_IN + b*TSEQ + t]
                                         : sm[OFF_OUT + b];
                    acc[b] = ffma2(wxv, dup2(x), bv);
                }
            } else {
                #pragma unroll
                for (int b = 0; b < 8; ++b) acc[b] = 0ull;
            }
            matvec<13, 13>(W1T, hd1, acc, j0);
            #pragma unroll
            for (int b = 0; b < 8; ++b)
                *reinterpret_cast<ull*>(gout + b*GROW + j0) = acc[b];
        }
        __syncthreads();

        gates(sm + OFF_GA, sm + OFF_GB, hd, c1r, 0, tid);   // h1 -> hdup[0..2H)
        __syncthreads();

        // ---- matvec layer 2 (partial over this warp's K-half) ----
        {
            ull acc[8];
            if (kh == 0) {
                ull bv = *reinterpret_cast<const ull*>(sm + OFF_B2 + j0);
                #pragma unroll
                for (int b = 0; b < 8; ++b) acc[b] = bv;
            } else {
                #pragma unroll
                for (int b = 0; b < 8; ++b) acc[b] = 0ull;
            }
            matvec<26, 13>(W2T, hd2, acc, j0);
            #pragma unroll
            for (int b = 0; b < 8; ++b)
                *reinterpret_cast<ull*>(gout + b*GROW + j0) = acc[b];
        }
        __syncthreads();

        gates(sm + OFF_GA, sm + OFF_GB, hd, c2r, H, tid);   // h2 -> hdup[2H..4H)
        __syncthreads();

        // ---- output: out[b] = h2 . Wl + bl ; warp wid handles batch wid ----
        {
            const float* h2p = hd + wid*HROW + 2*H;
            float p = h2p[2*lane] * sm[OFF_WL + lane];
            if (lane + 32 < H)
                p += h2p[2*(lane + 32)] * sm[OFF_WL + lane + 32];
            #pragma unroll
            for (int o = 16; o > 0; o >>= 1)
                p += __shfl_xor_sync(0xffffffffu, p, o);
            if (lane == 0) {
                float ov = p + sm[OFF_BL];
                out[(b0 + wid)*TTOT + t] = ov;
                sm[OFF_OUT + wid] = ov;   // feeds future-phase x
            }
        }
        __syncthreads();
    }
}

extern "C" void kernel_launch(void* const* d_in, const int* in_sizes, int n_in,
                              void* d_out, int out_size)
{
    (void)n_in; (void)out_size;
    cudaFuncSetAttribute(lstm_seq_kernel,
                         cudaFuncAttributeMaxDynamicSharedMemorySize, SMEM_BYTES);
    int nblocks = in_sizes[0] / (TSEQ * BB);   // B / 8 = 128
    lstm_seq_kernel<<<nblocks, NT, SMEM_BYTES>>>(
        (const float*)d_in[0],  (const float*)d_in[1], (const float*)d_in[2],
        (const float*)d_in[3],  (const float*)d_in[4], (const float*)d_in[5],
        (const float*)d_in[6],  (const float*)d_in[7], (const float*)d_in[8],
        (const float*)d_in[9],  (const float*)d_in[10],
        (float*)d_out);
}

// round 3
// speedup vs baseline: 1.2912x; 1.2901x over previous
#include <cuda_runtime.h>
#include <cstdint>

typedef unsigned long long ull;

#define H     51
#define G4    (4*H)       // 204 real gates
#define GP    256         // padded gate count
#define GROW  260         // g row stride (floats)
#define HROW  212         // hdup row stride (floats): 2*104=208 -> 212
#define BB    8           // batch per block
#define TSEQ  512
#define FUT   64
#define TTOT  (TSEQ + FUT)
#define NT    256         // 8 warps: 2 j-slices x 4 k-splits
#define NKS   4           // split-K factor

// ---- smem layout (float offsets) ----
#define OFF_W1T  0
#define SZ_W1T   (52*GP)                  // 13312
#define OFF_W2T  (OFF_W1T + SZ_W1T)
#define SZ_W2T   (104*GP)                 // 26624
#define OFF_WX   (OFF_W2T + SZ_W2T)
#define OFF_B1   (OFF_WX + GP)
#define OFF_B2   (OFF_B1 + GP)
#define OFF_WL   (OFF_B2 + GP)
#define OFF_IN   (OFF_WL + 64)
#define SZ_IN    (BB*TSEQ)                // 4096
#define OFF_HD   (OFF_IN + SZ_IN)
#define SZ_HD    (BB*HROW)                // 1696
#define OFF_G    (OFF_HD + SZ_HD)
#define SZ_G     (BB*GROW)                // 2080 per split buffer
#define OFF_OUT  (OFF_G + NKS*SZ_G)
#define OFF_BL   (OFF_OUT + 8)
#define SMEM_FLOATS (OFF_BL + 4)          // 54892 -> 219568 B
#define SMEM_BYTES  (SMEM_FLOATS * 4)

__device__ __forceinline__ ull ffma2(ull a, ull b, ull c) {
    ull d;
    asm("fma.rn.f32x2 %0, %1, %2, %3;" : "=l"(d) : "l"(a), "l"(b), "l"(c));
    return d;
}

__device__ __forceinline__ ull dup2(float v) {
    ull r;
    unsigned u = __float_as_uint(v);
    asm("mov.b64 %0, {%1, %2};" : "=l"(r) : "r"(u), "r"(u));
    return r;
}

__device__ __forceinline__ float fsig(float x) {
    float e = __expf(-x);
    return __fdividef(1.0f, 1.0f + e);
}

__device__ __forceinline__ float ftanh_acc(float x) {
    float a = fabsf(x);
    float e = __expf(-2.0f * a);           // <= 1, no overflow
    float r = __fdividef(1.0f - e, 1.0f + e);
    return copysignf(r, x);
}

// Partial matvec over NPAIR k-pairs for 4 gates/lane (j0..j0+3), 8 batches.
// Per kp: 2 weight LDS.128 + 8 broadcast-h LDS.128 feed 32 FFMA2 (0.5 wf/FFMA2).
template<int NPAIR>
__device__ __forceinline__ void matvec(const float* __restrict__ WT,
                                       const float* __restrict__ hd,
                                       ull acc0[8], ull acc1[8], int j0)
{
    #pragma unroll
    for (int kp = 0; kp < NPAIR; ++kp) {
        ulonglong2 w0 = *reinterpret_cast<const ulonglong2*>(WT + (2*kp  )*GP + j0);
        ulonglong2 w1 = *reinterpret_cast<const ulonglong2*>(WT + (2*kp+1)*GP + j0);
        #pragma unroll
        for (int b = 0; b < 8; ++b) {
            // (h[2kp],h[2kp], h[2kp+1],h[2kp+1]) — pre-duplicated pairs, broadcast
            ulonglong2 hv = *reinterpret_cast<const ulonglong2*>(hd + b*HROW + 4*kp);
            acc0[b] = ffma2(w0.x, hv.x, acc0[b]);
            acc1[b] = ffma2(w0.y, hv.x, acc1[b]);
            acc0[b] = ffma2(w1.x, hv.y, acc0[b]);
            acc1[b] = ffma2(w1.y, hv.y, acc1[b]);
        }
    }
}

__device__ __forceinline__ void store_acc(float* __restrict__ gout,
                                          ull acc0[8], ull acc1[8], int j0)
{
    #pragma unroll
    for (int b = 0; b < 8; ++b)
        *reinterpret_cast<ulonglong2*>(gout + b*GROW + j0) =
            make_ulonglong2(acc0[b], acc1[b]);
}

// gate nonlinearity: 408 (b,h) tasks over 256 threads; sums the 4 split-K
// partial buffers (reduction folded in); c state lives in registers.
__device__ __forceinline__ void gates(const float* __restrict__ g,
                                      float* __restrict__ hd,
                                      float creg[2], int hoff, int tid)
{
    #pragma unroll
    for (int i = 0; i < 2; ++i) {
        int tt = tid + i*NT;
        if (tt < BB*H) {
            int b = tt & 7, h = tt >> 3;
            int base = b*GROW + h;
            float gi = 0.f, gf = 0.f, gg = 0.f, go = 0.f;
            #pragma unroll
            for (int s = 0; s < NKS; ++s) {
                const float* gr = g + s*SZ_G + base;
                gi += gr[0];
                gf += gr[H];
                gg += gr[2*H];
                go += gr[3*H];
            }
            float c  = fsig(gf)*creg[i] + fsig(gi)*ftanh_acc(gg);
            float hn = fsig(go)*ftanh_acc(c);
            creg[i] = c;
            *reinterpret_cast<float2*>(hd + b*HROW + 2*(hoff + h)) = make_float2(hn, hn);
        }
    }
}

__global__ void __launch_bounds__(NT, 1)
lstm_seq_kernel(const float* __restrict__ input,
                const float* __restrict__ Wih1, const float* __restrict__ Whh1,
                const float* __restrict__ bih1, const float* __restrict__ bhh1,
                const float* __restrict__ Wih2, const float* __restrict__ Whh2,
                const float* __restrict__ bih2, const float* __restrict__ bhh2,
                const float* __restrict__ Wl,   const float* __restrict__ bl,
                float* __restrict__ out)
{
    extern __shared__ __align__(16) float sm[];
    const int tid = threadIdx.x;
    const int b0  = blockIdx.x * BB;

    // ---------- one-time prep: stage transposed/padded weights & inputs ----------
    for (int idx = tid; idx < SZ_W1T; idx += NT) {
        int k = idx >> 8, j = idx & 255;
        sm[OFF_W1T + idx] = (j < G4 && k < H) ? Whh1[j*H + k] : 0.0f;
    }
    for (int idx = tid; idx < SZ_W2T; idx += NT) {
        int k = idx >> 8, j = idx & 255;
        float v = 0.0f;
        if (j < G4) {
            if (k < H)        v = Wih2[j*H + k];
            else if (k < 2*H) v = Whh2[j*H + (k - H)];
        }
        sm[OFF_W2T + idx] = v;
    }
    for (int j = tid; j < GP; j += NT) {
        bool r = (j < G4);
        sm[OFF_WX + j] = r ? Wih1[j] : 0.0f;
        sm[OFF_B1 + j] = r ? (bih1[j] + bhh1[j]) : 0.0f;
        sm[OFF_B2 + j] = r ? (bih2[j] + bhh2[j]) : 0.0f;
    }
    if (tid < 64) sm[OFF_WL + tid] = (tid < H) ? Wl[tid] : 0.0f;
    for (int idx = tid; idx < SZ_IN; idx += NT)
        sm[OFF_IN + idx] = input[b0*TSEQ + idx];     // 8 contiguous rows
    for (int idx = tid; idx < SZ_HD; idx += NT) sm[OFF_HD + idx] = 0.0f;
    for (int idx = tid; idx < NKS*SZ_G; idx += NT) sm[OFF_G + idx] = 0.0f;
    if (tid < 8)   sm[OFF_OUT + tid] = 0.0f;
    if (tid == 0)  sm[OFF_BL] = bl[0];
    __syncthreads();

    float c1r[2] = {0.f, 0.f};
    float c2r[2] = {0.f, 0.f};

    const int wid  = tid >> 5, lane = tid & 31;
    const int js   = wid & 1;                // j-slice (2 x 128 gates)
    const int kh   = wid >> 1;               // k-split group (0..3)
    const int j0   = js*128 + lane*4;        // 4 consecutive gates per lane
    float* gout = sm + OFF_G + kh*SZ_G;

    // layer1 k-pair split {7,7,6,6} over 26 pairs; layer2 13 pairs each of 52
    const int s1 = (kh < 2) ? kh*7 : 14 + (kh - 2)*6;   // layer1 start pair
    const int s2 = kh*13;                               // layer2 start pair
    const float* W1T = sm + OFF_W1T + s1*2*GP;
    const float* W2T = sm + OFF_W2T + s2*2*GP;
    const float* hd1 = sm + OFF_HD + s1*4;
    const float* hd2 = sm + OFF_HD + s2*4;
    float* hd = sm + OFF_HD;

    for (int t = 0; t < TTOT; ++t) {
        // ---- matvec layer 1 (partial over this warp's k-range) ----
        {
            ull acc0[8], acc1[8];
            if (kh == 0) {
                ulonglong2 bv  = *reinterpret_cast<const ulonglong2*>(sm + OFF_B1 + j0);
                ulonglong2 wxv = *reinterpret_cast<const ulonglong2*>(sm + OFF_WX + j0);
                #pragma unroll
                for (int b = 0; b < 8; ++b) {
                    float x = (t < TSEQ) ? sm[OFF_IN + b*TSEQ + t]
                                         : sm[OFF_OUT + b];
                    ull xx = dup2(x);
                    acc0[b] = ffma2(wxv.x, xx, bv.x);
                    acc1[b] = ffma2(wxv.y, xx, bv.y);
                }
            } else {
                #pragma unroll
                for (int b = 0; b < 8; ++b) { acc0[b] = 0ull; acc1[b] = 0ull; }
            }
            if (kh < 2) matvec<7>(W1T, hd1, acc0, acc1, j0);
            else        matvec<6>(W1T, hd1, acc0, acc1, j0);
            store_acc(gout, acc0, acc1, j0);
        }
        __syncthreads();

        gates(sm + OFF_G, hd, c1r, 0, tid);   // h1 -> hdup[0..2H)
        __syncthreads();

        // ---- matvec layer 2 (partial over this warp's k-range) ----
        {
            ull acc0[8], acc1[8];
            if (kh == 0) {
                ulonglong2 bv = *reinterpret_cast<const ulonglong2*>(sm + OFF_B2 + j0);
                #pragma unroll
                for (int b = 0; b < 8; ++b) { acc0[b] = bv.x; acc1[b] = bv.y; }
            } else {
                #pragma unroll
                for (int b = 0; b < 8; ++b) { acc0[b] = 0ull; acc1[b] = 0ull; }
            }
            matvec<13>(W2T, hd2, acc0, acc1, j0);
            store_acc(gout, acc0, acc1, j0);
        }
        __syncthreads();

        gates(sm + OFF_G, hd, c2r, H, tid);   // h2 -> hdup[2H..4H)
        __syncthreads();

        // ---- output: out[b] = h2 . Wl + bl ; warp wid handles batch wid ----
        {
            const float* h2p = hd + wid*HROW + 2*H;
            float p = h2p[2*lane] * sm[OFF_WL + lane];
            if (lane + 32 < H)
                p += h2p[2*(lane + 32)] * sm[OFF_WL + lane + 32];
            #pragma unroll
            for (int o = 16; o > 0; o >>= 1)
                p += __shfl_xor_sync(0xffffffffu, p, o);
            if (lane == 0) {
                float ov = p + sm[OFF_BL];
                out[(b0 + wid)*TTOT + t] = ov;
                sm[OFF_OUT + wid] = ov;   // feeds future-phase x
            }
        }
        __syncthreads();
    }
}

extern "C" void kernel_launch(void* const* d_in, const int* in_sizes, int n_in,
                              void* d_out, int out_size)
{
    (void)n_in; (void)out_size;
    cudaFuncSetAttribute(lstm_seq_kernel,
                         cudaFuncAttributeMaxDynamicSharedMemorySize, SMEM_BYTES);
    int nblocks = in_sizes[0] / (TSEQ * BB);   // B / 8 = 128
    lstm_seq_kernel<<<nblocks, NT, SMEM_BYTES>>>(
        (const float*)d_in[0],  (const float*)d_in[1], (const float*)d_in[2],
        (const float*)d_in[3],  (const float*)d_in[4], (const float*)d_in[5],
        (const float*)d_in[6],  (const float*)d_in[7], (const float*)d_in[8],
        (const float*)d_in[9],  (const float*)d_in[10],
        (float*)d_out);
}